// round 1
// baseline (speedup 1.0000x reference)
#include <cuda_runtime.h>
#include <math.h>

// MaskAlignmentLoss: chamfer-style loss between 2D verts and valid mask pixels.
// B=4, N=6890, H=W=64. Output: single float32 scalar.

#define BATCH   4
#define NV      6890
#define HH      64
#define WW      64
#define HW      4096
#define INF2    1.0e18f        // (BIG=1e9)^2 sentinel for squared distances
#define VCHUNKS 8
#define PCHUNKS 4
#define VCH_LEN ((NV + VCHUNKS - 1) / VCHUNKS)   // 862
#define PCH_MAX ((HW + PCHUNKS - 1) / PCHUNKS)   // 1024

// -------- device scratch (no allocations allowed) --------
__device__ float2 g_pts[BATCH][HW];   // compacted normalized valid pixel coords
__device__ int    g_cnt[BATCH];       // valid pixel count per batch
__device__ int    g_pixmin[BATCH * HW];  // min d^2 per valid pixel slot (float bits)
__device__ int    g_vertmin[BATCH * NV]; // min d^2 per vert (float bits)

// -------- kernel 0: init sentinels (graph replays need fresh state) --------
__global__ void k_init() {
    int i = blockIdx.x * blockDim.x + threadIdx.x;
    int bits = __float_as_int(INF2);
    if (i < BATCH * HW) g_pixmin[i] = bits;
    if (i < BATCH * NV) g_vertmin[i] = bits;
}

// -------- kernel 1: deterministic compaction of valid pixels --------
// One block per batch, 256 threads, 16 pixels/thread, block-wide exclusive scan.
__global__ void k_compact(const int* __restrict__ mask) {
    int b = blockIdx.x;
    int tid = threadIdx.x;
    const int* m = mask + b * HW;
    int base = tid * 16;

    unsigned vbits = 0;
    int c = 0;
#pragma unroll
    for (int k = 0; k < 16; k++) {
        int v = (m[base + k] > 0) ? 1 : 0;
        vbits |= (unsigned)v << k;
        c += v;
    }

    int lane = tid & 31, wid = tid >> 5;
    int incl = c;
#pragma unroll
    for (int d = 1; d < 32; d <<= 1) {
        int t = __shfl_up_sync(0xffffffffu, incl, d);
        if (lane >= d) incl += t;
    }

    __shared__ int wtot[8], woff[8];
    if (lane == 31) wtot[wid] = incl;
    __syncthreads();
    if (tid < 8) {
        int v = wtot[tid];
        int s = v;
#pragma unroll
        for (int d = 1; d < 8; d <<= 1) {
            int t = __shfl_up_sync(0xffu, s, d);
            if (tid >= d) s += t;
        }
        woff[tid] = s - v;
        if (tid == 7) g_cnt[b] = s;
    }
    __syncthreads();

    int off = woff[wid] + (incl - c);
#pragma unroll
    for (int k = 0; k < 16; k++) {
        if ((vbits >> k) & 1u) {
            int p = base + k;
            float px = (float)(p & (WW - 1)) * (1.0f / WW);
            float py = (float)(p >> 6)       * (1.0f / HH);
            g_pts[b][off++] = make_float2(px, py);
        }
    }
}

// -------- kernel 2: pixel-major pass (term1: min over verts per valid pixel) --------
// grid: (HW/256 pixel blocks, VCHUNKS, BATCH)
__global__ void k_pass1(const float* __restrict__ vert) {
    int b = blockIdx.z;
    int cnt = g_cnt[b];
    if ((int)(blockIdx.x * 256) >= cnt) return;   // uniform early exit

    int vc   = blockIdx.y;
    int v0   = vc * VCH_LEN;
    int vlen = min(VCH_LEN, NV - v0);

    __shared__ float2 sv[VCH_LEN];
    const float* vb = vert + (size_t)b * NV * 2;
    for (int j = threadIdx.x; j < vlen; j += 256) {
        sv[j] = make_float2(vb[(size_t)(v0 + j) * 2]     * (1.0f / WW),
                            vb[(size_t)(v0 + j) * 2 + 1] * (1.0f / HH));
    }
    __syncthreads();

    int i = blockIdx.x * 256 + threadIdx.x;
    bool act = (i < cnt);
    float px = 0.f, py = 0.f;
    if (act) { float2 p = g_pts[b][i]; px = p.x; py = p.y; }

    float mn = INF2;
#pragma unroll 4
    for (int j = 0; j < vlen; j++) {
        float2 v = sv[j];
        float dx = px - v.x;
        float dy = py - v.y;
        float d2 = fmaf(dx, dx, dy * dy);
        mn = fminf(mn, d2);
    }
    if (act) atomicMin(&g_pixmin[b * HW + i], __float_as_int(mn));
}

// -------- kernel 3: vert-major pass (term2: min over valid pixels per vert) --------
// grid: (ceil(NV/256), PCHUNKS, BATCH)
__global__ void k_pass2(const float* __restrict__ vert) {
    int b = blockIdx.z;
    int cnt = g_cnt[b];
    int pc = blockIdx.y;
    int plen_full = (cnt + PCHUNKS - 1) / PCHUNKS;
    int p0 = pc * plen_full;
    int plen = min(plen_full, cnt - p0);
    if (plen <= 0) return;

    __shared__ float2 sp[PCH_MAX];
    for (int j = threadIdx.x; j < plen; j += 256) sp[j] = g_pts[b][p0 + j];
    __syncthreads();

    int n = blockIdx.x * 256 + threadIdx.x;
    bool act = (n < NV);
    float vx = 0.f, vy = 0.f;
    if (act) {
        const float* vb = vert + ((size_t)b * NV + n) * 2;
        vx = vb[0] * (1.0f / WW);
        vy = vb[1] * (1.0f / HH);
    }

    float mn = INF2;
#pragma unroll 4
    for (int j = 0; j < plen; j++) {
        float2 p = sp[j];
        float dx = vx - p.x;
        float dy = vy - p.y;
        mn = fminf(mn, fmaf(dx, dx, dy * dy));
    }
    if (act) atomicMin(&g_vertmin[b * NV + n], __float_as_int(mn));
}

// -------- kernel 4: deterministic final reduction (sqrt at the end) --------
__global__ void k_reduce(float* __restrict__ out) {
    int tid = threadIdx.x;   // 256 threads, 1 block
    float s = 0.f;
    for (int b = 0; b < BATCH; b++) {
        int cnt = g_cnt[b];
        for (int i = tid; i < cnt; i += 256)
            s += sqrtf(__int_as_float(g_pixmin[b * HW + i]));
    }
    for (int j = tid; j < BATCH * NV; j += 256)
        s += sqrtf(__int_as_float(g_vertmin[j]));

    __shared__ float red[256];
    red[tid] = s;
    __syncthreads();
#pragma unroll
    for (int d = 128; d > 0; d >>= 1) {
        if (tid < d) red[tid] += red[tid + d];
        __syncthreads();
    }
    if (tid == 0) out[0] = red[0];   // LOSS_WEIGHT = 1
}

extern "C" void kernel_launch(void* const* d_in, const int* in_sizes, int n_in,
                              void* d_out, int out_size) {
    const float* vert2d = (const float*)d_in[0];   // [B, N, 2] float32
    const int*   mask   = (const int*)d_in[1];     // [B, H, W] int32
    float* out = (float*)d_out;

    (void)in_sizes; (void)n_in; (void)out_size;

    int init_total = BATCH * HW + BATCH * NV;      // take max of the two ranges
    int init_blocks = (init_total + 255) / 256;
    k_init<<<init_blocks, 256>>>();

    k_compact<<<BATCH, 256>>>(mask);

    dim3 g1(HW / 256, VCHUNKS, BATCH);
    k_pass1<<<g1, 256>>>(vert2d);

    dim3 g2((NV + 255) / 256, PCHUNKS, BATCH);
    k_pass2<<<g2, 256>>>(vert2d);

    k_reduce<<<1, 256>>>(out);
}

// round 2
// speedup vs baseline: 1.4697x; 1.4697x over previous
#include <cuda_runtime.h>
#include <math.h>

// MaskAlignmentLoss: chamfer-style loss, B=4, N=6890, H=W=64, fp32 scalar out.

#define BATCH   4
#define NV      6890
#define HH      64
#define WW      64
#define HW      4096
#define INF2    1.0e18f
#define VCHUNKS 8
#define PCHUNKS 4
#define VCH_LEN ((NV + VCHUNKS - 1) / VCHUNKS)      // 862 (even)
#define PCH_MAX ((HW + PCHUNKS - 1) / PCHUNKS)      // 1024
#define NSLOT_MAX (PCH_MAX / 2 + 1)                 // 513 packed slots
#define SENT    (-1.0e9f)                           // negated far-away sentinel

// -------- device scratch --------
__device__ float2 g_pts[BATCH][HW];
__device__ int    g_cnt[BATCH];
__device__ int    g_pixmin[BATCH * HW];
__device__ int    g_vertmin[BATCH * NV];
#define TOTMIN (BATCH * HW + BATCH * NV)            // 43944

// -------- packed f32x2 helpers (sm_103a) --------
typedef unsigned long long u64;
__device__ __forceinline__ u64 pk(float a, float b) {
    u64 r; asm("mov.b64 %0, {%1, %2};" : "=l"(r) : "f"(a), "f"(b)); return r;
}
__device__ __forceinline__ void upk(u64 v, float& a, float& b) {
    asm("mov.b64 {%0, %1}, %2;" : "=f"(a), "=f"(b) : "l"(v));
}
__device__ __forceinline__ u64 add2(u64 a, u64 b) {
    u64 r; asm("add.rn.f32x2 %0, %1, %2;" : "=l"(r) : "l"(a), "l"(b)); return r;
}
__device__ __forceinline__ u64 mul2(u64 a, u64 b) {
    u64 r; asm("mul.rn.f32x2 %0, %1, %2;" : "=l"(r) : "l"(a), "l"(b)); return r;
}
__device__ __forceinline__ u64 fma2(u64 a, u64 b, u64 c) {
    u64 r; asm("fma.rn.f32x2 %0, %1, %2, %3;" : "=l"(r) : "l"(a), "l"(b), "l"(c)); return r;
}
__device__ __forceinline__ float sqrt_ap(float x) {
    float r; asm("sqrt.approx.f32 %0, %1;" : "=f"(r) : "f"(x)); return r;
}

// ======== kernel 0: init sentinels + zero out + compact valid pixels ========
// grid 48 x 256. All blocks stride-init; blocks 0..3 also compact batch b.
__global__ void k_setup(const int* __restrict__ mask, float* __restrict__ out) {
    int gid = blockIdx.x * 256 + threadIdx.x;
    int bits = __float_as_int(INF2);
    for (int i = gid; i < TOTMIN; i += 48 * 256) {
        if (i < BATCH * HW) g_pixmin[i] = bits;
        else                g_vertmin[i - BATCH * HW] = bits;
    }
    if (gid == 0) out[0] = 0.0f;

    if (blockIdx.x >= BATCH) return;
    int b = blockIdx.x;
    int tid = threadIdx.x;
    const int* m = mask + b * HW;
    int base = tid * 16;

    unsigned vbits = 0; int c = 0;
#pragma unroll
    for (int k = 0; k < 16; k++) {
        int v = (m[base + k] > 0) ? 1 : 0;
        vbits |= (unsigned)v << k;
        c += v;
    }
    int lane = tid & 31, wid = tid >> 5;
    int incl = c;
#pragma unroll
    for (int d = 1; d < 32; d <<= 1) {
        int t = __shfl_up_sync(0xffffffffu, incl, d);
        if (lane >= d) incl += t;
    }
    __shared__ int wtot[8], woff[8];
    if (lane == 31) wtot[wid] = incl;
    __syncthreads();
    if (tid < 8) {
        int v = wtot[tid], s = v;
#pragma unroll
        for (int d = 1; d < 8; d <<= 1) {
            int t = __shfl_up_sync(0xffu, s, d);
            if (tid >= d) s += t;
        }
        woff[tid] = s - v;
        if (tid == 7) g_cnt[b] = s;
    }
    __syncthreads();
    int off = woff[wid] + (incl - c);
#pragma unroll
    for (int k = 0; k < 16; k++) {
        if ((vbits >> k) & 1u) {
            int p = base + k;
            g_pts[b][off++] = make_float2((float)(p & (WW - 1)) * (1.0f / WW),
                                          (float)(p >> 6)       * (1.0f / HH));
        }
    }
}

// ======== kernel 1: fused pairwise passes (packed f32x2 inner loop) ========
// grid (27, 8, 8): z in [0,4) -> pass1 (pixel-major), z in [4,8) -> pass2.
// smem holds NEGATED candidate coords as float4 (-x0,-x1,-y0,-y1) per slot.
__global__ void __launch_bounds__(256) k_pairs(const float* __restrict__ vert) {
    __shared__ float4 sXY[NSLOT_MAX];
    int b = blockIdx.z & 3;
    int cnt = g_cnt[b];

    if (blockIdx.z < BATCH) {
        // ---------- pass1: per valid pixel, min over vert chunk ----------
        if (blockIdx.x >= HW / 256) return;
        if ((int)(blockIdx.x * 256) >= cnt) return;
        int v0 = blockIdx.y * VCH_LEN;
        int vlen = min(VCH_LEN, NV - v0);
        int nslots = (vlen + 1) >> 1;

        const float* vb = vert + (size_t)b * NV * 2;
        for (int s = threadIdx.x; s < nslots; s += 256) {
            int j0 = v0 + 2 * s, j1 = j0 + 1;
            // two consecutive verts = 4 consecutive floats (16B aligned: j0 even, b*NV even)
            float4 q = *reinterpret_cast<const float4*>(vb + (size_t)j0 * 2); // (x0,y0,x1,y1)
            float x0 = -q.x * (1.0f / WW), y0 = -q.y * (1.0f / HH);
            float x1, y1;
            if (j1 < v0 + vlen) { x1 = -q.z * (1.0f / WW); y1 = -q.w * (1.0f / HH); }
            else                { x1 = SENT; y1 = SENT; }
            sXY[s] = make_float4(x0, x1, y0, y1);
        }
        __syncthreads();

        int i = blockIdx.x * 256 + threadIdx.x;
        bool act = (i < cnt);
        float px = 0.f, py = 0.f;
        if (act) { float2 p = g_pts[b][i]; px = p.x; py = p.y; }
        u64 PX = pk(px, px), PY = pk(py, py);

        float mn0 = INF2, mn1 = INF2;
#pragma unroll 4
        for (int s = 0; s < nslots; s++) {
            float4 q = sXY[s];
            u64 dX = add2(PX, pk(q.x, q.y));
            u64 dY = add2(PY, pk(q.z, q.w));
            u64 D  = fma2(dX, dX, mul2(dY, dY));
            float lo, hi; upk(D, lo, hi);
            mn0 = fminf(mn0, lo);
            mn1 = fminf(mn1, hi);
        }
        if (act) atomicMin(&g_pixmin[b * HW + i], __float_as_int(fminf(mn0, mn1)));
    } else {
        // ---------- pass2: per vert, min over valid-pixel chunk ----------
        if (blockIdx.y >= PCHUNKS) return;
        int plen_full = (cnt + PCHUNKS - 1) / PCHUNKS;
        int p0 = blockIdx.y * plen_full;
        int plen = min(plen_full, cnt - p0);
        if (plen <= 0) return;
        int nslots = (plen + 1) >> 1;

        for (int s = threadIdx.x; s < nslots; s += 256) {
            int j0 = p0 + 2 * s, j1 = j0 + 1;
            float2 a = g_pts[b][j0];
            float x0 = -a.x, y0 = -a.y;
            float x1 = SENT, y1 = SENT;
            if (j1 < p0 + plen) { float2 c2 = g_pts[b][j1]; x1 = -c2.x; y1 = -c2.y; }
            sXY[s] = make_float4(x0, x1, y0, y1);
        }
        __syncthreads();

        int n = blockIdx.x * 256 + threadIdx.x;
        bool act = (n < NV);
        float vx = 0.f, vy = 0.f;
        if (act) {
            const float* vb = vert + ((size_t)b * NV + n) * 2;
            vx = vb[0] * (1.0f / WW);
            vy = vb[1] * (1.0f / HH);
        }
        u64 VX = pk(vx, vx), VY = pk(vy, vy);

        float mn0 = INF2, mn1 = INF2;
#pragma unroll 4
        for (int s = 0; s < nslots; s++) {
            float4 q = sXY[s];
            u64 dX = add2(VX, pk(q.x, q.y));
            u64 dY = add2(VY, pk(q.z, q.w));
            u64 D  = fma2(dX, dX, mul2(dY, dY));
            float lo, hi; upk(D, lo, hi);
            mn0 = fminf(mn0, lo);
            mn1 = fminf(mn1, hi);
        }
        if (act) atomicMin(&g_vertmin[b * NV + n], __float_as_int(fminf(mn0, mn1)));
    }
}

// ======== kernel 2: parallel sqrt + sum (43 blocks, atomicAdd) ========
__global__ void k_sum(float* __restrict__ out) {
    int base = blockIdx.x * 1024 + threadIdx.x;
    float s = 0.f;
#pragma unroll
    for (int k = 0; k < 4; k++) {
        int i = base + k * 256;
        if (i < TOTMIN) {
            float v;
            if (i < BATCH * HW) {
                v = __int_as_float(g_pixmin[i]);
                if (v >= 1.0e17f) v = 0.f;      // untouched slot (invalid pixel) -> 0
            } else {
                v = __int_as_float(g_vertmin[i - BATCH * HW]);
                // untouched (cnt==0) stays INF2 -> sqrt = 1e9 = BIG, matching reference
            }
            s += sqrt_ap(fmaxf(v, 0.f));
        }
    }
    // block reduce
    __shared__ float red[256];
    red[threadIdx.x] = s;
    __syncthreads();
#pragma unroll
    for (int d = 128; d > 0; d >>= 1) {
        if (threadIdx.x < d) red[threadIdx.x] += red[threadIdx.x + d];
        __syncthreads();
    }
    if (threadIdx.x == 0) atomicAdd(out, red[0]);
}

extern "C" void kernel_launch(void* const* d_in, const int* in_sizes, int n_in,
                              void* d_out, int out_size) {
    const float* vert2d = (const float*)d_in[0];
    const int*   mask   = (const int*)d_in[1];
    float* out = (float*)d_out;
    (void)in_sizes; (void)n_in; (void)out_size;

    k_setup<<<48, 256>>>(mask, out);

    dim3 g(27, 8, 2 * BATCH);
    k_pairs<<<g, 256>>>(vert2d);

    k_sum<<<(TOTMIN + 1023) / 1024, 256>>>(out);
}